// round 9
// baseline (speedup 1.0000x reference)
#include <cuda_runtime.h>
#include <cuda_bf16.h>

// out[b, j, k] = sum_d x[b, j+1, d] * W[j, d, k] + bias[j, k]
// B = 65536, NODES = 13, D = 256, J = 12, K = 2
//
// Persistent-j warps: total warps is a multiple of 12; warp w owns joint
// j = w % 12 and grid-strides over groups of RB=4 batch rows. W[j] (4 x
// float4 per lane) and bias[j] are loaded ONCE into registers, so the loop
// body issues only the 2 minimum coalesced x wavefronts per output row
// (__ldcs, pure streaming). Reduction is a merged butterfly: 16 shuffles for
// all 8 accumulators, finishing with each sum in a distinct lane quad, then
// one predicated scattered STG.32.

#define NODES 13
#define DIM   256
#define NJ    12
#define RB    4

__global__ void __launch_bounds__(256)
detok_kernel(const float* __restrict__ x,
             const float* __restrict__ W,
             const float* __restrict__ bias,
             float* __restrict__ out,
             int B)
{
    int wid  = (blockIdx.x * blockDim.x + threadIdx.x) >> 5;
    int lane = threadIdx.x & 31;
    int total_warps = (gridDim.x * blockDim.x) >> 5;   // multiple of 12

    int j  = wid % NJ;                 // fixed joint for this warp
    int g0 = wid / NJ;                 // first batch group
    int gstride = total_warps / NJ;
    int node = j + 1;
    int ngroups = (B + RB - 1) / RB;

    // ---- W[j] resident in registers for the whole kernel ----
    const float4* __restrict__ wr =
        reinterpret_cast<const float4*>(W + j * (DIM * 2));
    float4 wa0 = wr[2 * lane];         // d-block 4*lane,   k interleaved
    float4 wa1 = wr[2 * lane + 1];
    float4 wb0 = wr[64 + 2 * lane];    // d-block 128+4*lane
    float4 wb1 = wr[64 + 2 * lane + 1];

    // bias component this lane will write (see store mapping below)
    float2 bj = reinterpret_cast<const float2*>(bias)[j];
    int k_out = (lane >> 4) & 1;                       // 0 or 1
    int r_out = ((lane >> 3) & 1) + 2 * ((lane >> 2) & 1);
    float b_out = k_out ? bj.y : bj.x;
    bool writer = (lane & 3) == 0;

    for (int g = g0; g < ngroups; g += gstride) {
        int b0 = g * RB;

        // ---- front-batched streaming x loads: 8 x LDG.128 ----
        float4 x0[RB], x1[RB];
#pragma unroll
        for (int r = 0; r < RB; r++) {
            if (b0 + r < B) {
                const float4* __restrict__ xr = reinterpret_cast<const float4*>(
                    x + ((long long)(b0 + r) * NODES + node) * DIM);
                x0[r] = __ldcs(xr + lane);
                x1[r] = __ldcs(xr + lane + 32);
            } else {
                x0[r] = make_float4(0.f, 0.f, 0.f, 0.f);
                x1[r] = make_float4(0.f, 0.f, 0.f, 0.f);
            }
        }

        // ---- partial dot products: a[2r+k] ----
        float a[2 * RB];
#pragma unroll
        for (int r = 0; r < RB; r++) {
            a[2 * r]     = x0[r].x * wa0.x + x0[r].y * wa0.z
                         + x0[r].z * wa1.x + x0[r].w * wa1.z
                         + x1[r].x * wb0.x + x1[r].y * wb0.z
                         + x1[r].z * wb1.x + x1[r].w * wb1.z;
            a[2 * r + 1] = x0[r].x * wa0.y + x0[r].y * wa0.w
                         + x0[r].z * wa1.y + x0[r].w * wa1.w
                         + x1[r].x * wb0.y + x1[r].y * wb0.w
                         + x1[r].z * wb1.y + x1[r].w * wb1.w;
        }

        // ---- merged butterfly reduction: 16 shuffles total ----
        // level off=16, then fold 8 values -> 4 (upper lane-half carries odd idx)
#pragma unroll
        for (int v = 0; v < 8; v++)
            a[v] += __shfl_xor_sync(0xFFFFFFFFu, a[v], 16);
        float m[4];
#pragma unroll
        for (int i = 0; i < 4; i++)
            m[i] = (lane & 16) ? a[2 * i + 1] : a[2 * i];

        // level off=8, fold 4 -> 2
#pragma unroll
        for (int i = 0; i < 4; i++)
            m[i] += __shfl_xor_sync(0xFFFFFFFFu, m[i], 8);
        float n[2];
        n[0] = (lane & 8) ? m[1] : m[0];
        n[1] = (lane & 8) ? m[3] : m[2];

        // level off=4, fold 2 -> 1
        n[0] += __shfl_xor_sync(0xFFFFFFFFu, n[0], 4);
        n[1] += __shfl_xor_sync(0xFFFFFFFFu, n[1], 4);
        float p = (lane & 4) ? n[1] : n[0];

        // finish within lane quads
        p += __shfl_xor_sync(0xFFFFFFFFu, p, 2);
        p += __shfl_xor_sync(0xFFFFFFFFu, p, 1);
        // lane l now holds sum of a[v], v = ((l>>4)&1) + 2*((l>>3)&1) + 4*((l>>2)&1)
        //   => k = (l>>4)&1, r = ((l>>3)&1) + 2*((l>>2)&1)

        if (writer && (b0 + r_out) < B) {
            out[((b0 + r_out) * NJ + j) * 2 + k_out] = p + b_out;
        }
    }
}

extern "C" void kernel_launch(void* const* d_in, const int* in_sizes, int n_in,
                              void* d_out, int out_size)
{
    const float* x    = (const float*)d_in[0];   // (B, 13, 256)
    const float* W    = (const float*)d_in[1];   // (12, 256, 2)
    const float* bias = (const float*)d_in[2];   // (12, 2)
    float* out = (float*)d_out;                  // (B, 12, 2)

    int B = in_sizes[0] / (NODES * DIM);

    const int threads = 256;     // 8 warps/CTA
    const int blocks  = 888;     // 148 SMs * 6; 888*8 = 7104 warps = 12 * 592
    detok_kernel<<<blocks, threads>>>(x, W, bias, out, B);
}

// round 12
// speedup vs baseline: 1.6013x; 1.6013x over previous
#include <cuda_runtime.h>
#include <cuda_bf16.h>

// out[b, j, k] = sum_d x[b, j+1, d] * W[j, d, k] + bias[j, k]
// B = 65536, NODES = 13, D = 256, J = 12, K = 2
//
// R4 shape (big grid, warp per (j, 4 batch rows), W amortized in registers)
// + merged butterfly reduction (16 SHFL for all 8 accumulators, each final
// sum landing in a distinct lane quad) + one predicated scattered STG.32
// from 8 lanes instead of 4 serialized lane-0 STG.64.

#define NODES 13
#define DIM   256
#define NJ    12
#define RB    4     // batch rows per warp

__global__ void __launch_bounds__(256)
detok_kernel(const float* __restrict__ x,
             const float* __restrict__ W,
             const float* __restrict__ bias,
             float* __restrict__ out)
{
    int gwarp = (blockIdx.x * blockDim.x + threadIdx.x) >> 5;
    int lane  = threadIdx.x & 31;

    int bg = gwarp / NJ;
    int j  = gwarp - bg * NJ;
    int b0 = bg * RB;
    int node = j + 1;

    // ---- W[j]: 256x2 floats. Lane l covers d in {4l..4l+3} and {128+4l..} ----
    const float4* __restrict__ wr =
        reinterpret_cast<const float4*>(W + j * (DIM * 2));
    float4 wa0 = wr[2 * lane];
    float4 wa1 = wr[2 * lane + 1];
    float4 wb0 = wr[64 + 2 * lane];
    float4 wb1 = wr[64 + 2 * lane + 1];

    // ---- front-batched streaming x loads: 8 outstanding LDG.128 per lane ----
    float4 x0[RB], x1[RB];
#pragma unroll
    for (int r = 0; r < RB; r++) {
        const float4* __restrict__ xr = reinterpret_cast<const float4*>(
            x + ((long long)(b0 + r) * NODES + node) * DIM);
        x0[r] = __ldcs(xr + lane);
        x1[r] = __ldcs(xr + lane + 32);
    }

    // ---- partial dot products: a[2r+k] ----
    float a[2 * RB];
#pragma unroll
    for (int r = 0; r < RB; r++) {
        a[2 * r]     = x0[r].x * wa0.x + x0[r].y * wa0.z
                     + x0[r].z * wa1.x + x0[r].w * wa1.z
                     + x1[r].x * wb0.x + x1[r].y * wb0.z
                     + x1[r].z * wb1.x + x1[r].w * wb1.z;
        a[2 * r + 1] = x0[r].x * wa0.y + x0[r].y * wa0.w
                     + x0[r].z * wa1.y + x0[r].w * wa1.w
                     + x1[r].x * wb0.y + x1[r].y * wb0.w
                     + x1[r].z * wb1.y + x1[r].w * wb1.w;
    }

    // ---- merged butterfly reduction: 16 SHFL total ----
    // After each butterfly level, fold the value set in half across a lane bit.
#pragma unroll
    for (int v = 0; v < 8; v++)
        a[v] += __shfl_xor_sync(0xFFFFFFFFu, a[v], 16);
    float m[4];
#pragma unroll
    for (int i = 0; i < 4; i++)
        m[i] = (lane & 16) ? a[2 * i + 1] : a[2 * i];

#pragma unroll
    for (int i = 0; i < 4; i++)
        m[i] += __shfl_xor_sync(0xFFFFFFFFu, m[i], 8);
    float n0 = (lane & 8) ? m[1] : m[0];
    float n1 = (lane & 8) ? m[3] : m[2];

    n0 += __shfl_xor_sync(0xFFFFFFFFu, n0, 4);
    n1 += __shfl_xor_sync(0xFFFFFFFFu, n1, 4);
    float p = (lane & 4) ? n1 : n0;

    p += __shfl_xor_sync(0xFFFFFFFFu, p, 2);
    p += __shfl_xor_sync(0xFFFFFFFFu, p, 1);
    // lane l holds the full sum for v = 2r+k with
    //   k = (l>>4)&1, r = ((l>>3)&1) + 2*((l>>2)&1)

    int k_out = (lane >> 4) & 1;
    int r_out = ((lane >> 3) & 1) + 2 * ((lane >> 2) & 1);
    if ((lane & 3) == 0) {
        float2 bj = reinterpret_cast<const float2*>(bias)[j];
        float b_out = k_out ? bj.y : bj.x;
        out[((b0 + r_out) * NJ + j) * 2 + k_out] = p + b_out;
    }
}

extern "C" void kernel_launch(void* const* d_in, const int* in_sizes, int n_in,
                              void* d_out, int out_size)
{
    const float* x    = (const float*)d_in[0];   // (B, 13, 256)
    const float* W    = (const float*)d_in[1];   // (12, 256, 2)
    const float* bias = (const float*)d_in[2];   // (12, 2)
    float* out = (float*)d_out;                  // (B, 12, 2)

    int B = in_sizes[0] / (NODES * DIM);

    const int threads = 256;                     // 8 warps/CTA
    int total_warps = (B / RB) * NJ;             // 196608
    int blocks = total_warps / (threads / 32);   // 24576, exact

    detok_kernel<<<blocks, threads>>>(x, W, bias, out);
}